// round 7
// baseline (speedup 1.0000x reference)
#include <cuda_runtime.h>

// StackMemory: reference scan only writes stack row 0 and reads row 1 (always
// zero), so:
//   out[0, t, 0, h] = softmax0(hs[t]·W^T + b) * sigmoid(hs[t]·D)  (all h equal)
//   out[0, t, d, h] = 0 for d >= 1
//
// One launch, two block roles (fill FIRST, compute LAST):
//   blocks [0, T): pure streaming zero-fill of the d>=1 region (406 MB).
//   blocks [T, T+T/32): compute. warp-per-t (4 t per warp), butterfly reduce,
//                     writes the 100-float4 val row for each t. ~26 MB.
//   Compute blocks are placed at the END of the grid so their DRAM reads land
//   in the tail wave instead of interleaving read/write bus turnarounds into
//   the saturated write stream of wave 1.
//
// NOTE (R3/R5 lessons): the fill-loop form below is load-bearing. Fully
// unrolling the store burst (R3) or peeling the 64B head for alignment (R5)
// both flipped ptxas into a store-issue schedule that saturates the L1tex
// wavefront queue (L1 ~83% busy, DRAM ~54%) and cost +23us. Do not perturb.

#define HID    400
#define DEPTH  32
#define ROW4   (DEPTH * HID / 4)   // 3200 float4 per timestep
#define VAL4   (HID / 4)           // 100 float4 val row
#define TPB    256

__global__ void __launch_bounds__(TPB, 8)
stackmem_kernel(const float* __restrict__ hs,
                const float* __restrict__ W,
                const float* __restrict__ b,
                const float* __restrict__ Dv,
                float* __restrict__ out,
                int n_fill_blocks) {
    if ((int)blockIdx.x < n_fill_blocks) {
        // ---------- pure zero-fill role ----------
        const int t = blockIdx.x;
        float4* __restrict__ o4 =
            reinterpret_cast<float4*>(out + (size_t)t * (DEPTH * HID)) + VAL4;
        const float4 zz = make_float4(0.f, 0.f, 0.f, 0.f);
        // 3100 float4, 256 threads -> 12 full iters + partial
        #pragma unroll 4
        for (int i = threadIdx.x; i < ROW4 - VAL4; i += TPB) {
            __stcs(&o4[i], zz);
        }
        return;
    }

    // ---------- compute role: warp per t, 4 t per warp ----------
    const int cb   = blockIdx.x - n_fill_blocks;
    const int wid  = threadIdx.x >> 5;
    const int lane = threadIdx.x & 31;
    const int t0   = cb * 32 + wid * 4;

    const float4* __restrict__ w0 = reinterpret_cast<const float4*>(W);
    const float4* __restrict__ w1 = reinterpret_cast<const float4*>(W + HID);
    const float4* __restrict__ w2 = reinterpret_cast<const float4*>(W + 2 * HID);
    const float4* __restrict__ d4 = reinterpret_cast<const float4*>(Dv);
    const float b0 = __ldg(&b[0]), b1 = __ldg(&b[1]), b2 = __ldg(&b[2]);

    #pragma unroll
    for (int k = 0; k < 4; k++) {
        const int t = t0 + k;
        const float4* __restrict__ x4 =
            reinterpret_cast<const float4*>(hs + (size_t)t * HID);

        float a0 = 0.f, a1 = 0.f, a2 = 0.f, a3 = 0.f;
        for (int i = lane; i < VAL4; i += 32) {
            float4 x = __ldg(&x4[i]);
            float4 p;
            p = __ldg(&w0[i]); a0 += x.x*p.x + x.y*p.y + x.z*p.z + x.w*p.w;
            p = __ldg(&w1[i]); a1 += x.x*p.x + x.y*p.y + x.z*p.z + x.w*p.w;
            p = __ldg(&w2[i]); a2 += x.x*p.x + x.y*p.y + x.z*p.z + x.w*p.w;
            p = __ldg(&d4[i]); a3 += x.x*p.x + x.y*p.y + x.z*p.z + x.w*p.w;
        }

        // Butterfly reduce: every lane ends with the full sum (no broadcast).
        #pragma unroll
        for (int o = 16; o > 0; o >>= 1) {
            a0 += __shfl_xor_sync(0xFFFFFFFFu, a0, o);
            a1 += __shfl_xor_sync(0xFFFFFFFFu, a1, o);
            a2 += __shfl_xor_sync(0xFFFFFFFFu, a2, o);
            a3 += __shfl_xor_sync(0xFFFFFFFFu, a3, o);
        }

        const float l0 = a0 + b0, l1 = a1 + b1, l2 = a2 + b2;
        const float m  = fmaxf(l0, fmaxf(l1, l2));
        const float e0 = __expf(l0 - m);
        const float e1 = __expf(l1 - m);
        const float e2 = __expf(l2 - m);
        const float p0 = e0 / (e0 + e1 + e2);
        const float pv = 1.0f / (1.0f + __expf(-a3));
        const float v  = p0 * pv;
        const float4 vv = make_float4(v, v, v, v);

        float4* __restrict__ o4 =
            reinterpret_cast<float4*>(out + (size_t)t * (DEPTH * HID));
        for (int i = lane; i < VAL4; i += 32) {
            __stcs(&o4[i], vv);
        }
    }
}

extern "C" void kernel_launch(void* const* d_in, const int* in_sizes, int n_in,
                              void* d_out, int out_size) {
    const float* hs = (const float*)d_in[0];   // (1, T, 400)
    const float* W  = (const float*)d_in[1];   // (3, 400)
    const float* b  = (const float*)d_in[2];   // (3,)
    const float* Dv = (const float*)d_in[3];   // (1, 400)
    float* out = (float*)d_out;                // (1, T, 32, 400)

    const int T = in_sizes[0] / HID;           // 8192 (B=1)
    const int n_compute = T / 32;              // 256 compute blocks (warp x4 t)
    stackmem_kernel<<<T + n_compute, TPB>>>(hs, W, b, Dv, out, T);
}

// round 8
// speedup vs baseline: 1.0736x; 1.0736x over previous
#include <cuda_runtime.h>

// StackMemory — FINAL (R2 form, reproduced at 63.39/63.36us).
//
// The reference scan only writes stack row 0 and reads row 1 (always zero), so:
//   out[0, t, 0, h] = softmax0(hs[t]·W^T + b) * sigmoid(hs[t]·D)  (all h equal)
//   out[0, t, d, h] = 0 for d >= 1
// => 433 MB mandatory traffic (419 MB writes + 13 MB reads), moved at
//    ~6.8 TB/s wall-effective. Information-theoretic traffic minimum.
//
// One launch, two block roles (compute FIRST so its latency-bound prologue
// overlaps the fill stream — R7 showed compute-at-end exposes it as a serial
// tail, +4.8us):
//   blocks [0, T/32): compute. warp-per-t (4 t per warp), butterfly reduce,
//                     writes the 100-float4 val row for each t. ~26 MB traffic.
//   blocks [T/32, T/32+T): pure streaming zero-fill of the d>=1 region.
//
// NOTE (R3/R5 lessons): this exact fill-loop form is load-bearing. Fully
// unrolling the store burst (R3) or peeling the 64B head for alignment (R5)
// both flipped ptxas into a store-issue schedule that saturates the L1tex
// wavefront queue (L1 ~83% busy, DRAM ~54%) and cost +23us. Do not perturb.

#define HID    400
#define DEPTH  32
#define ROW4   (DEPTH * HID / 4)   // 3200 float4 per timestep
#define VAL4   (HID / 4)           // 100 float4 val row
#define TPB    256

__global__ void __launch_bounds__(TPB, 8)
stackmem_kernel(const float* __restrict__ hs,
                const float* __restrict__ W,
                const float* __restrict__ b,
                const float* __restrict__ Dv,
                float* __restrict__ out,
                int n_compute_blocks) {
    if ((int)blockIdx.x >= n_compute_blocks) {
        // ---------- pure zero-fill role ----------
        const int t = blockIdx.x - n_compute_blocks;
        float4* __restrict__ o4 =
            reinterpret_cast<float4*>(out + (size_t)t * (DEPTH * HID)) + VAL4;
        const float4 zz = make_float4(0.f, 0.f, 0.f, 0.f);
        // 3100 float4, 256 threads -> 12 full iters + partial
        #pragma unroll 4
        for (int i = threadIdx.x; i < ROW4 - VAL4; i += TPB) {
            __stcs(&o4[i], zz);
        }
        return;
    }

    // ---------- compute role: warp per t, 4 t per warp ----------
    const int wid  = threadIdx.x >> 5;
    const int lane = threadIdx.x & 31;
    const int t0   = blockIdx.x * 32 + wid * 4;

    const float4* __restrict__ w0 = reinterpret_cast<const float4*>(W);
    const float4* __restrict__ w1 = reinterpret_cast<const float4*>(W + HID);
    const float4* __restrict__ w2 = reinterpret_cast<const float4*>(W + 2 * HID);
    const float4* __restrict__ d4 = reinterpret_cast<const float4*>(Dv);
    const float b0 = __ldg(&b[0]), b1 = __ldg(&b[1]), b2 = __ldg(&b[2]);

    #pragma unroll
    for (int k = 0; k < 4; k++) {
        const int t = t0 + k;
        const float4* __restrict__ x4 =
            reinterpret_cast<const float4*>(hs + (size_t)t * HID);

        float a0 = 0.f, a1 = 0.f, a2 = 0.f, a3 = 0.f;
        for (int i = lane; i < VAL4; i += 32) {
            float4 x = __ldg(&x4[i]);
            float4 p;
            p = __ldg(&w0[i]); a0 += x.x*p.x + x.y*p.y + x.z*p.z + x.w*p.w;
            p = __ldg(&w1[i]); a1 += x.x*p.x + x.y*p.y + x.z*p.z + x.w*p.w;
            p = __ldg(&w2[i]); a2 += x.x*p.x + x.y*p.y + x.z*p.z + x.w*p.w;
            p = __ldg(&d4[i]); a3 += x.x*p.x + x.y*p.y + x.z*p.z + x.w*p.w;
        }

        // Butterfly reduce: every lane ends with the full sum (no broadcast).
        #pragma unroll
        for (int o = 16; o > 0; o >>= 1) {
            a0 += __shfl_xor_sync(0xFFFFFFFFu, a0, o);
            a1 += __shfl_xor_sync(0xFFFFFFFFu, a1, o);
            a2 += __shfl_xor_sync(0xFFFFFFFFu, a2, o);
            a3 += __shfl_xor_sync(0xFFFFFFFFu, a3, o);
        }

        const float l0 = a0 + b0, l1 = a1 + b1, l2 = a2 + b2;
        const float m  = fmaxf(l0, fmaxf(l1, l2));
        const float e0 = __expf(l0 - m);
        const float e1 = __expf(l1 - m);
        const float e2 = __expf(l2 - m);
        const float p0 = e0 / (e0 + e1 + e2);
        const float pv = 1.0f / (1.0f + __expf(-a3));
        const float v  = p0 * pv;
        const float4 vv = make_float4(v, v, v, v);

        float4* __restrict__ o4 =
            reinterpret_cast<float4*>(out + (size_t)t * (DEPTH * HID));
        for (int i = lane; i < VAL4; i += 32) {
            __stcs(&o4[i], vv);
        }
    }
}

extern "C" void kernel_launch(void* const* d_in, const int* in_sizes, int n_in,
                              void* d_out, int out_size) {
    const float* hs = (const float*)d_in[0];   // (1, T, 400)
    const float* W  = (const float*)d_in[1];   // (3, 400)
    const float* b  = (const float*)d_in[2];   // (3,)
    const float* Dv = (const float*)d_in[3];   // (1, 400)
    float* out = (float*)d_out;                // (1, T, 32, 400)

    const int T = in_sizes[0] / HID;           // 8192 (B=1)
    const int n_compute = T / 32;              // 256 compute blocks (warp x4 t)
    stackmem_kernel<<<n_compute + T, TPB>>>(hs, W, b, Dv, out, n_compute);
}

// round 9
// speedup vs baseline: 1.1082x; 1.0322x over previous
#include <cuda_runtime.h>

// StackMemory — warp-specialized single-role variant.
//
// Reference scan only writes stack row 0 and reads row 1 (always zero), so:
//   out[0, t, 0, h] = softmax0(hs[t]·W^T + b) * sigmoid(hs[t]·D)  (all h equal)
//   out[0, t, d, h] = 0 for d >= 1
//
// 8192 uniform blocks, one per timestep, NO barriers:
//   warp 0   : computes the scalar (100-float4 dot x4, butterfly reduce) and
//              writes the 100-float4 val row.
//   warps 1-7: zero-fill the 3100-float4 d>=1 region (stride 224, paced
//              strided loop — R3/R5 showed unrolled bursts / head peeling
//              flip ptxas into an L1tex-saturating store schedule, +23us).
// Compute-warp DRAM latency hides behind sibling fill warps in-block.
// Fallback if this regresses: R2 two-role form (reproduced 3x at 63.4us).

#define HID    400
#define DEPTH  32
#define ROW4   (DEPTH * HID / 4)   // 3200 float4 per timestep
#define VAL4   (HID / 4)           // 100 float4 val row
#define ZERO4  (ROW4 - VAL4)       // 3100 float4 zero region
#define TPB    256

__global__ void __launch_bounds__(TPB, 8)
stackmem_kernel(const float* __restrict__ hs,
                const float* __restrict__ W,
                const float* __restrict__ b,
                const float* __restrict__ Dv,
                float* __restrict__ out) {
    const int t    = blockIdx.x;
    const int wid  = threadIdx.x >> 5;
    const int lane = threadIdx.x & 31;

    float4* __restrict__ o4 =
        reinterpret_cast<float4*>(out + (size_t)t * (DEPTH * HID));

    if (wid != 0) {
        // ---------- fill warps (1..7): 224 threads over 3100 float4 ----------
        float4* __restrict__ z4 = o4 + VAL4;
        const float4 zz = make_float4(0.f, 0.f, 0.f, 0.f);
        #pragma unroll 4
        for (int i = threadIdx.x - 32; i < ZERO4; i += (TPB - 32)) {
            __stcs(&z4[i], zz);
        }
        return;
    }

    // ---------- warp 0: compute val for this t ----------
    const float4* __restrict__ x4 =
        reinterpret_cast<const float4*>(hs + (size_t)t * HID);
    const float4* __restrict__ w0 = reinterpret_cast<const float4*>(W);
    const float4* __restrict__ w1 = reinterpret_cast<const float4*>(W + HID);
    const float4* __restrict__ w2 = reinterpret_cast<const float4*>(W + 2 * HID);
    const float4* __restrict__ d4 = reinterpret_cast<const float4*>(Dv);

    float a0 = 0.f, a1 = 0.f, a2 = 0.f, a3 = 0.f;
    for (int i = lane; i < VAL4; i += 32) {
        float4 x = __ldg(&x4[i]);
        float4 p;
        p = __ldg(&w0[i]); a0 += x.x*p.x + x.y*p.y + x.z*p.z + x.w*p.w;
        p = __ldg(&w1[i]); a1 += x.x*p.x + x.y*p.y + x.z*p.z + x.w*p.w;
        p = __ldg(&w2[i]); a2 += x.x*p.x + x.y*p.y + x.z*p.z + x.w*p.w;
        p = __ldg(&d4[i]); a3 += x.x*p.x + x.y*p.y + x.z*p.z + x.w*p.w;
    }

    // Butterfly reduce: every lane ends with the full sum (no broadcast).
    #pragma unroll
    for (int o = 16; o > 0; o >>= 1) {
        a0 += __shfl_xor_sync(0xFFFFFFFFu, a0, o);
        a1 += __shfl_xor_sync(0xFFFFFFFFu, a1, o);
        a2 += __shfl_xor_sync(0xFFFFFFFFu, a2, o);
        a3 += __shfl_xor_sync(0xFFFFFFFFu, a3, o);
    }

    const float l0 = a0 + __ldg(&b[0]);
    const float l1 = a1 + __ldg(&b[1]);
    const float l2 = a2 + __ldg(&b[2]);
    const float m  = fmaxf(l0, fmaxf(l1, l2));
    const float e0 = __expf(l0 - m);
    const float e1 = __expf(l1 - m);
    const float e2 = __expf(l2 - m);
    const float p0 = e0 / (e0 + e1 + e2);
    const float pv = 1.0f / (1.0f + __expf(-a3));
    const float v  = p0 * pv;
    const float4 vv = make_float4(v, v, v, v);

    for (int i = lane; i < VAL4; i += 32) {
        __stcs(&o4[i], vv);
    }
}

extern "C" void kernel_launch(void* const* d_in, const int* in_sizes, int n_in,
                              void* d_out, int out_size) {
    const float* hs = (const float*)d_in[0];   // (1, T, 400)
    const float* W  = (const float*)d_in[1];   // (3, 400)
    const float* b  = (const float*)d_in[2];   // (3,)
    const float* Dv = (const float*)d_in[3];   // (1, 400)
    float* out = (float*)d_out;                // (1, T, 32, 400)

    const int T = in_sizes[0] / HID;           // 8192 (B=1)
    stackmem_kernel<<<T, TPB>>>(hs, W, b, Dv, out);
}